// round 10
// baseline (speedup 1.0000x reference)
#include <cuda_runtime.h>
#include <cuda_bf16.h>
#include <stdint.h>

#define NB 96
#define NQ 96
#define NV 197
#define NT 77
#define ND 768
#define NE 512
#define RV (NB*NV)
#define RT (NQ*NT)

// scratch (static device globals — no allocation allowed)
__device__ float g_Pv[RV*NE];
__device__ float g_Pt[RT*NE];
__device__ __nv_bfloat16 g_vtok[RV*NE];
__device__ __nv_bfloat16 g_ttok[RT*NE];
__device__ float g_cm[2][NB*NQ*80];   // per-half column maxima
__device__ float g_rs[2][NB*NQ];      // per-half row-max partial sums

__device__ __forceinline__ uint32_t smem_u32(const void* p){
    return (uint32_t)__cvta_generic_to_shared(p);
}
__device__ __forceinline__ void cp16(uint32_t dst, const void* src, int sz){
    asm volatile("cp.async.cg.shared.global [%0], [%1], 16, %2;\n"
                 :: "r"(dst), "l"(src), "r"(sz));
}
__device__ __forceinline__ void cp_commit(){ asm volatile("cp.async.commit_group;\n"); }
template<int N> __device__ __forceinline__ void cp_wait(){
    asm volatile("cp.async.wait_group %0;\n" :: "n"(N));
}
__device__ __forceinline__ uint32_t f2tf(float f){
    uint32_t u; asm("cvt.rna.tf32.f32 %0, %1;\n" : "=r"(u) : "f"(f)); return u;
}
__device__ __forceinline__ void mma_bf16(float c[4], const uint32_t a[4], const uint32_t b[2]){
    asm volatile(
      "mma.sync.aligned.m16n8k16.row.col.f32.bf16.bf16.f32 "
      "{%0,%1,%2,%3},{%4,%5,%6,%7},{%8,%9},{%0,%1,%2,%3};\n"
      : "+f"(c[0]),"+f"(c[1]),"+f"(c[2]),"+f"(c[3])
      : "r"(a[0]),"r"(a[1]),"r"(a[2]),"r"(a[3]),"r"(b[0]),"r"(b[1]));
}
__device__ __forceinline__ void mma_tf32(float c[4], const uint32_t a[4], const uint32_t b[2]){
    asm volatile(
      "mma.sync.aligned.m16n8k8.row.col.f32.tf32.tf32.f32 "
      "{%0,%1,%2,%3},{%4,%5,%6,%7},{%8,%9},{%0,%1,%2,%3};\n"
      : "+f"(c[0]),"+f"(c[1]),"+f"(c[2]),"+f"(c[3])
      : "r"(a[0]),"r"(a[1]),"r"(a[2]),"r"(a[3]),"r"(b[0]),"r"(b[1]));
}
__device__ __forceinline__ void ldsm_x4(uint32_t r[4], uint32_t addr){
    asm volatile("ldmatrix.sync.aligned.m8n8.x4.shared.b16 {%0,%1,%2,%3}, [%4];"
                 : "=r"(r[0]), "=r"(r[1]), "=r"(r[2]), "=r"(r[3]) : "r"(addr));
}
__device__ __forceinline__ void ldsm_x2(uint32_t r[2], uint32_t addr){
    asm volatile("ldmatrix.sync.aligned.m8n8.x2.shared.b16 {%0,%1}, [%2];"
                 : "=r"(r[0]), "=r"(r[1]) : "r"(addr));
}

// ---------------------------------------------------------------------------
// K1: cls projections (pure FP32, accuracy-critical outputs)
// ---------------------------------------------------------------------------
__global__ __launch_bounds__(256) void cls_gemm(
    const float* __restrict__ Xv, const float* __restrict__ Xt,
    const float* __restrict__ Wv, const float* __restrict__ bv,
    const float* __restrict__ Wt, const float* __restrict__ bt,
    float* __restrict__ out)
{
    __shared__ float Xs[16][64];
    __shared__ float Ws[64][65];
    const int which = blockIdx.z;
    const float* X    = which ? Xt : Xv;
    const float* W    = which ? Wt : Wv;
    const float* bias = which ? bt : bv;
    const int m0 = blockIdx.x * 16;
    const int n0 = blockIdx.y * 64;
    const int tid = threadIdx.x;
    float acc[4] = {0.f,0.f,0.f,0.f};
    const int jj = tid & 63;
    const int r4 = (tid >> 6) * 4;

    for (int k0 = 0; k0 < ND; k0 += 64){
        {
            int r = tid >> 4, kv = tid & 15;
            float4 x4 = *(const float4*)(X + (size_t)(m0 + r)*ND + k0 + kv*4);
            Xs[r][kv*4+0]=x4.x; Xs[r][kv*4+1]=x4.y; Xs[r][kv*4+2]=x4.z; Xs[r][kv*4+3]=x4.w;
        }
        #pragma unroll
        for (int i = 0; i < 4; i++){
            int seg = tid + 256*i; int r = seg >> 4, kv = seg & 15;
            float4 w4 = *(const float4*)(W + (size_t)(n0 + r)*ND + k0 + kv*4);
            Ws[r][kv*4+0]=w4.x; Ws[r][kv*4+1]=w4.y; Ws[r][kv*4+2]=w4.z; Ws[r][kv*4+3]=w4.w;
        }
        __syncthreads();
        #pragma unroll
        for (int k = 0; k < 64; k++){
            float w = Ws[jj][k];
            acc[0] += Xs[r4+0][k]*w;
            acc[1] += Xs[r4+1][k]*w;
            acc[2] += Xs[r4+2][k]*w;
            acc[3] += Xs[r4+3][k]*w;
        }
        __syncthreads();
    }
    float bb = bias[n0 + jj];
    float* o = out + (size_t)which*(NB*NE);
    #pragma unroll
    for (int i = 0; i < 4; i++)
        o[(size_t)(m0 + r4 + i)*NE + n0 + jj] = acc[i] + bb;
}

// ---------------------------------------------------------------------------
// K2: token projection GEMM (TF32 mma.sync m16n8k8)
// ---------------------------------------------------------------------------
__global__ __launch_bounds__(256,2) void tok_gemm(
    const float* __restrict__ X, const float* __restrict__ W,
    const float* __restrict__ bias, int R, int which)
{
    __shared__ float As[2][128][20];
    __shared__ float Bs[2][128][20];
    float* P = which ? g_Pt : g_Pv;
    const int m0 = blockIdx.x*128, n0 = blockIdx.y*128;
    const int tid = threadIdx.x, lane = tid & 31, warp = tid >> 5;
    const int wm = warp & 1, wn = warp >> 1;
    float acc[4][4][4] = {};
    const uint32_t aB = smem_u32(&As[0][0][0]);
    const uint32_t bB = smem_u32(&Bs[0][0][0]);

    auto loadP = [&](int buf, int kc){
        const int k0 = kc*16;
        #pragma unroll
        for (int i = 0; i < 2; i++){
            int seg = tid + 256*i; int r = seg >> 2, kv = seg & 3;
            uint32_t dst = aB + (uint32_t)(buf*128*20 + r*20 + kv*4)*4;
            int gr = m0 + r;
            const float* src = X + (size_t)(gr < R ? gr : 0)*ND + k0 + kv*4;
            cp16(dst, src, gr < R ? 16 : 0);
        }
        #pragma unroll
        for (int i = 0; i < 2; i++){
            int seg = tid + 256*i; int r = seg >> 2, kv = seg & 3;
            uint32_t dst = bB + (uint32_t)(buf*128*20 + r*20 + kv*4)*4;
            const float* src = W + (size_t)(n0 + r)*ND + k0 + kv*4;
            cp16(dst, src, 16);
        }
    };

    loadP(0, 0); cp_commit();
    for (int kc = 0; kc < 48; kc++){
        if (kc < 47){ loadP((kc+1)&1, kc+1); cp_commit(); cp_wait<1>(); }
        else        { cp_wait<0>(); }
        __syncthreads();
        const int buf = kc & 1;
        #pragma unroll
        for (int ks = 0; ks < 2; ks++){
            const int kk = ks*8 + (lane & 3);
            uint32_t a[4][4], bfr[4][2];
            #pragma unroll
            for (int mt = 0; mt < 4; mt++){
                int r = wm*64 + mt*16 + (lane >> 2);
                a[mt][0] = f2tf(As[buf][r  ][kk  ]);
                a[mt][1] = f2tf(As[buf][r+8][kk  ]);
                a[mt][2] = f2tf(As[buf][r  ][kk+4]);
                a[mt][3] = f2tf(As[buf][r+8][kk+4]);
            }
            #pragma unroll
            for (int nt = 0; nt < 4; nt++){
                int n = wn*32 + nt*8 + (lane >> 2);
                bfr[nt][0] = f2tf(Bs[buf][n][kk  ]);
                bfr[nt][1] = f2tf(Bs[buf][n][kk+4]);
            }
            #pragma unroll
            for (int mt = 0; mt < 4; mt++)
                #pragma unroll
                for (int nt = 0; nt < 4; nt++)
                    mma_tf32(acc[mt][nt], a[mt], bfr[nt]);
        }
        __syncthreads();
    }
    #pragma unroll
    for (int mt = 0; mt < 4; mt++){
        #pragma unroll
        for (int nt = 0; nt < 4; nt++){
            int r = m0 + wm*64 + mt*16 + (lane >> 2);
            int c = n0 + wn*32 + nt*8 + (lane & 3)*2;
            float b0 = bias[c], b1 = bias[c+1];
            if (r < R){
                P[(size_t)r*NE + c  ] = acc[mt][nt][0] + b0;
                P[(size_t)r*NE + c+1] = acc[mt][nt][1] + b1;
            }
            if (r + 8 < R){
                P[(size_t)(r+8)*NE + c  ] = acc[mt][nt][2] + b0;
                P[(size_t)(r+8)*NE + c+1] = acc[mt][nt][3] + b1;
            }
        }
    }
}

// ---------------------------------------------------------------------------
// K3: l2-normalize rows of P -> bf16 tokens
// ---------------------------------------------------------------------------
__global__ __launch_bounds__(256) void norm_kernel(int R, int which)
{
    const float* P = which ? g_Pt : g_Pv;
    __nv_bfloat16* O = which ? g_ttok : g_vtok;
    const int row  = blockIdx.x*8 + (threadIdx.x >> 5);
    const int lane = threadIdx.x & 31;
    if (row >= R) return;
    const float4* p = (const float4*)(P + (size_t)row*NE);
    float4 v[4]; float ss = 0.f;
    #pragma unroll
    for (int i = 0; i < 4; i++){
        v[i] = p[lane + 32*i];
        ss += v[i].x*v[i].x + v[i].y*v[i].y + v[i].z*v[i].z + v[i].w*v[i].w;
    }
    #pragma unroll
    for (int o = 16; o > 0; o >>= 1) ss += __shfl_xor_sync(0xffffffffu, ss, o);
    const float s = 1.f / fmaxf(sqrtf(ss), 1e-12f);
    uint2* ob = (uint2*)(O + (size_t)row*NE);
    #pragma unroll
    for (int i = 0; i < 4; i++){
        __nv_bfloat162 lo = __floats2bfloat162_rn(v[i].x*s, v[i].y*s);
        __nv_bfloat162 hi = __floats2bfloat162_rn(v[i].z*s, v[i].w*s);
        uint2 u; u.x = *(uint32_t*)&lo; u.y = *(uint32_t*)&hi;
        ob[lane + 32*i] = u;
    }
}

// ---------------------------------------------------------------------------
// K4: fine-grained similarity, M-split + q-pairing + LENGTH-AWARE column-tile
// skipping. Grid (48, 96, 2); CTA 256 thr, 8 warps (4x2), warp tile 32x40
// per q, two q's per CTA (A reused). Columns >= len are never computed:
// each warp computes ntc_j = ceil((len_j - wn*40)/8) of its 5 n-tiles, and
// B rows >= ceil8(len_j) are neither loaded nor read. Exact (masked entries
// are discarded by construction). acc = 80 regs, 2 CTAs/SM.
// ---------------------------------------------------------------------------
#define FG7_SMEM 83968
#define ASTRIDE 144          // 72 bf16 per row

__global__ __launch_bounds__(256,2) void fg7_kernel(
    const int* __restrict__ text_length)
{
    extern __shared__ char smem[];
    // [0, 36864): A[2buf][128][72] bf16
    // [36864, 82944): B[2q][2buf][80][72] bf16
    const uint32_t aB = smem_u32(smem);
    const uint32_t bB = aB + 36864;
    float* rowp = (float*)smem;            // [2q][2wn][128]  epilogue overlay
    float* colp = (float*)(smem + 4096);   // [2q][4wm][80]
    float* red  = (float*)(smem + 6656);   // [2q][8]

    const int q0 = blockIdx.x*2, b = blockIdx.y, z = blockIdx.z;
    const int m_base = z*128;
    const int mrows  = z ? 80 : 128;       // loaded rows
    const int vlim   = z ? 69 : 128;       // valid local rows
    const int tid = threadIdx.x, lane = tid & 31, warp = tid >> 5;
    const int wm = warp >> 1, wn = warp & 1;
    const int mtcnt = (z == 0) ? 2 : (wm < 2 ? 2 : (wm == 2 ? 1 : 0));
    const __nv_bfloat16* Ag  = g_vtok + (size_t)b*NV*NE;
    const __nv_bfloat16* Bg0 = g_ttok + (size_t)q0*NT*NE;
    const __nv_bfloat16* Bg1 = g_ttok + (size_t)(q0+1)*NT*NE;
    float acc[2][2][5][4] = {};   // [q][mt][nt][4]

    const int len0 = text_length[q0];
    const int len1 = text_length[q0+1];
    // per-warp valid n-tile counts (tiles of 8 cols within this warp's 40)
    int t0 = (len0 - wn*40 + 7) >> 3; if (t0 < 0) t0 = 0; if (t0 > 5) t0 = 5;
    int t1 = (len1 - wn*40 + 7) >> 3; if (t1 < 0) t1 = 0; if (t1 > 5) t1 = 5;
    const int ntc0 = t0, ntc1 = t1;
    const bool anyA = (ntc0 + ntc1) > 0 && mtcnt > 0;
    const int blim0 = (len0 + 7) & ~7;   // B rows to load (round up to 8)
    const int blim1 = (len1 + 7) & ~7;

    const uint32_t a_lane = aB + (uint32_t)(wm*32 + (lane & 15))*ASTRIDE
                               + (uint32_t)((lane >> 4) & 1)*16;
    const uint32_t b_pat  = (uint32_t)(wn*40 + (lane & 7) + ((lane >> 4) & 1)*8)*ASTRIDE
                               + (uint32_t)((lane >> 3) & 1)*16;

    auto loadc = [&](int buf, int kc){
        const int k0 = kc*64;
        for (int seg = tid; seg < mrows*8; seg += 256){
            int r = seg >> 3, kv = seg & 7;
            uint32_t dst = aB + (uint32_t)buf*18432 + (uint32_t)r*ASTRIDE + (uint32_t)kv*16;
            int gr = m_base + r;
            const __nv_bfloat16* src = Ag + (size_t)(gr < NV ? gr : 0)*NE + k0 + kv*8;
            cp16(dst, src, gr < NV ? 16 : 0);
        }
        #pragma unroll
        for (int i = 0; i < 5; i++){
            int seg = tid + 256*i;
            if (seg < 1280){
                int j  = seg / 640;
                int s2 = seg - j*640;
                int r = s2 >> 3, kv = s2 & 7;
                int len  = j ? len1 : len0;
                int blim = j ? blim1 : blim0;
                if (r < blim){
                    uint32_t dst = bB + (uint32_t)j*23040 + (uint32_t)buf*11520
                                 + (uint32_t)r*ASTRIDE + (uint32_t)kv*16;
                    const __nv_bfloat16* src = (j ? Bg1 : Bg0)
                                               + (size_t)(r < len ? r : 0)*NE + k0 + kv*8;
                    cp16(dst, src, r < len ? 16 : 0);   // ragged edge zero-filled
                }
            }
        }
    };

    loadc(0, 0); cp_commit();
    for (int kc = 0; kc < 8; kc++){
        if (kc < 7){ loadc((kc+1)&1, kc+1); cp_commit(); cp_wait<1>(); }
        else       { cp_wait<0>(); }
        __syncthreads();
        const uint32_t abuf = a_lane + (uint32_t)(kc & 1)*18432;
        const uint32_t b0   = bB + b_pat + (uint32_t)(kc & 1)*11520;
        const uint32_t b1   = b0 + 23040;
        #pragma unroll
        for (int ks = 0; ks < 4; ks++){
            const uint32_t ko = (uint32_t)ks*32;
            uint32_t a[2][4], bf0[10], bf1[10];
            if (anyA){
                #pragma unroll
                for (int mt = 0; mt < 2; mt++)
                    if (mt < mtcnt) ldsm_x4(a[mt], abuf + (uint32_t)mt*(16*ASTRIDE) + ko);
            }
            if (ntc0 > 0) ldsm_x4(&bf0[0], b0 + ko);
            if (ntc0 > 2) ldsm_x4(&bf0[4], b0 + 16*ASTRIDE + ko);
            if (ntc0 > 4) ldsm_x2(&bf0[8], b0 + 32*ASTRIDE + ko);
            if (ntc1 > 0) ldsm_x4(&bf1[0], b1 + ko);
            if (ntc1 > 2) ldsm_x4(&bf1[4], b1 + 16*ASTRIDE + ko);
            if (ntc1 > 4) ldsm_x2(&bf1[8], b1 + 32*ASTRIDE + ko);
            #pragma unroll
            for (int mt = 0; mt < 2; mt++)
                if (mt < mtcnt){
                    #pragma unroll
                    for (int nt = 0; nt < 5; nt++){
                        if (nt < ntc0) mma_bf16(acc[0][mt][nt], a[mt], &bf0[nt*2]);
                        if (nt < ntc1) mma_bf16(acc[1][mt][nt], a[mt], &bf1[nt*2]);
                    }
                }
        }
        __syncthreads();
    }

    // ---- epilogue: register-space masked reductions, per q ----
    const float NEG = -3.0e38f;

    #pragma unroll
    for (int j = 0; j < 2; j++){
        const int len = j ? len1 : len0;
        // row maxima over this warp's 40 cols (masked c < len)
        #pragma unroll
        for (int mt = 0; mt < 2; mt++){
            if (mt < mtcnt){
                float m0 = NEG, m1 = NEG;
                #pragma unroll
                for (int nt = 0; nt < 5; nt++){
                    int c0 = wn*40 + nt*8 + (lane & 3)*2;
                    if (c0 < len){ m0 = fmaxf(m0, acc[j][mt][nt][0]); m1 = fmaxf(m1, acc[j][mt][nt][2]); }
                    if (c0 + 1 < len){ m0 = fmaxf(m0, acc[j][mt][nt][1]); m1 = fmaxf(m1, acc[j][mt][nt][3]); }
                }
                m0 = fmaxf(m0, __shfl_xor_sync(0xffffffffu, m0, 1));
                m0 = fmaxf(m0, __shfl_xor_sync(0xffffffffu, m0, 2));
                m1 = fmaxf(m1, __shfl_xor_sync(0xffffffffu, m1, 1));
                m1 = fmaxf(m1, __shfl_xor_sync(0xffffffffu, m1, 2));
                if ((lane & 3) == 0){
                    int r = wm*32 + mt*16 + (lane >> 2);
                    rowp[j*256 + wn*128 + r]     = m0;
                    rowp[j*256 + wn*128 + r + 8] = m1;
                }
            } else if ((lane & 3) == 0){
                int r = wm*32 + mt*16 + (lane >> 2);
                rowp[j*256 + wn*128 + r]     = NEG;
                rowp[j*256 + wn*128 + r + 8] = NEG;
            }
        }
        // column maxima over this warp's rows (masked global r < NV)
        #pragma unroll
        for (int nt = 0; nt < 5; nt++){
            float c0m = NEG, c1m = NEG;
            #pragma unroll
            for (int mt = 0; mt < 2; mt++){
                if (mt < mtcnt){
                    int gr = m_base + wm*32 + mt*16 + (lane >> 2);
                    if (gr < NV){ c0m = fmaxf(c0m, acc[j][mt][nt][0]); c1m = fmaxf(c1m, acc[j][mt][nt][1]); }
                    if (gr + 8 < NV){ c0m = fmaxf(c0m, acc[j][mt][nt][2]); c1m = fmaxf(c1m, acc[j][mt][nt][3]); }
                }
            }
            #pragma unroll
            for (int o = 4; o <= 16; o <<= 1){
                c0m = fmaxf(c0m, __shfl_xor_sync(0xffffffffu, c0m, o));
                c1m = fmaxf(c1m, __shfl_xor_sync(0xffffffffu, c1m, o));
            }
            if (lane < 4){
                int c = wn*40 + nt*8 + lane*2;
                colp[j*320 + wm*80 + c]     = c0m;
                colp[j*320 + wm*80 + c + 1] = c1m;
            }
        }
    }
    __syncthreads();

    // rowsum partials (valid local rows; 0-clamp when len < NT)
    #pragma unroll
    for (int j = 0; j < 2; j++){
        const int len = j ? len1 : len0;
        float contrib = 0.f;
        if (tid < vlim){
            float r = fmaxf(rowp[j*256 + tid], rowp[j*256 + 128 + tid]);
            if (len < NT) r = fmaxf(r, 0.f);
            contrib = r;
        }
        #pragma unroll
        for (int o = 16; o > 0; o >>= 1) contrib += __shfl_xor_sync(0xffffffffu, contrib, o);
        if (lane == 0) red[j*8 + warp] = contrib;
    }
    __syncthreads();
    if (warp < 2){   // warp j finalizes q_j rowsum
        float s = (lane < 8) ? red[warp*8 + lane] : 0.f;
        #pragma unroll
        for (int o = 4; o > 0; o >>= 1) s += __shfl_xor_sync(0xffffffffu, s, o);
        if (lane == 0) g_rs[z][b*NQ + q0 + warp] = s;
    }
    if (tid < 160){
        int j = tid / 80, t = tid - j*80;
        float cm = fmaxf(fmaxf(colp[j*320 + t],       colp[j*320 + 80 + t]),
                         fmaxf(colp[j*320 + 160 + t], colp[j*320 + 240 + t]));
        g_cm[z][(size_t)(b*NQ + q0 + j)*80 + t] = cm;
    }
}

// ---------------------------------------------------------------------------
// K5: finish — combine the two M-halves. One warp per (b,q).
// ---------------------------------------------------------------------------
__global__ __launch_bounds__(256) void finish_kernel(
    const int* __restrict__ text_length, float* __restrict__ out)
{
    const int gw = blockIdx.x*8 + (threadIdx.x >> 5);
    const int lane = threadIdx.x & 31;
    if (gw >= NB*NQ) return;
    const int q = gw % NQ, b = gw / NQ;
    const int len = text_length[q];
    float ts = 0.f;
    for (int t = lane; t < len; t += 32)
        ts += fmaxf(g_cm[0][(size_t)gw*80 + t], g_cm[1][(size_t)gw*80 + t]);
    #pragma unroll
    for (int o = 16; o > 0; o >>= 1) ts += __shfl_xor_sync(0xffffffffu, ts, o);
    if (lane == 0){
        out[2*NB*NE         + (size_t)b*NQ + q] = ts / (float)len;                 // t2v
        out[2*NB*NE + NB*NQ + (size_t)b*NQ + q] = (g_rs[0][gw] + g_rs[1][gw]) / (float)NV; // v2t
    }
}

extern "C" void kernel_launch(void* const* d_in, const int* in_sizes, int n_in,
                              void* d_out, int out_size) {
    const float* visual_cls    = (const float*)d_in[0];
    const float* visual_tokens = (const float*)d_in[1];
    const float* textual_cls   = (const float*)d_in[2];
    const float* textual_tokens= (const float*)d_in[3];
    const float* Wv_cls = (const float*)d_in[4];
    const float* bv_cls = (const float*)d_in[5];
    const float* Wt_cls = (const float*)d_in[6];
    const float* bt_cls = (const float*)d_in[7];
    const float* Wv_tok = (const float*)d_in[8];
    const float* bv_tok = (const float*)d_in[9];
    const float* Wt_tok = (const float*)d_in[10];
    const float* bt_tok = (const float*)d_in[11];
    const int*   text_length = (const int*)d_in[12];
    float* out = (float*)d_out;

    static bool attr_done = false;
    if (!attr_done){
        cudaFuncSetAttribute(fg7_kernel, cudaFuncAttributeMaxDynamicSharedMemorySize, FG7_SMEM);
        attr_done = true;
    }

    cls_gemm<<<dim3(6,8,2), 256>>>(visual_cls, textual_cls,
                                   Wv_cls, bv_cls, Wt_cls, bt_cls, out);
    tok_gemm<<<dim3((RV+127)/128, 4), 256>>>(visual_tokens, Wv_tok, bv_tok, RV, 0);
    tok_gemm<<<dim3((RT+127)/128, 4), 256>>>(textual_tokens, Wt_tok, bt_tok, RT, 1);
    norm_kernel<<<RV/8, 256>>>(RV, 0);
    norm_kernel<<<RT/8, 256>>>(RT, 1);
    fg7_kernel<<<dim3(NQ/2, NB, 2), 256, FG7_SMEM>>>(text_length);
    finish_kernel<<<(NB*NQ + 7)/8, 256>>>(text_length, out);
}

// round 12
// speedup vs baseline: 1.2666x; 1.2666x over previous
#include <cuda_runtime.h>
#include <cuda_bf16.h>
#include <stdint.h>

#define NB 96
#define NQ 96
#define NV 197
#define NT 77
#define ND 768
#define NE 512
#define RV (NB*NV)
#define RT (NQ*NT)

// scratch (static device globals — no allocation allowed)
__device__ float g_Pv[RV*NE];
__device__ float g_Pt[RT*NE];
__device__ __nv_bfloat16 g_vtok[RV*NE];
__device__ __nv_bfloat16 g_ttok[RT*NE];
__device__ float g_cm[2][NB*NQ*80];   // per-half column maxima
__device__ float g_rs[2][NB*NQ];      // per-half row-max partial sums
// bf16 copies of token-GEMM inputs
__device__ __nv_bfloat16 g_Xvb[RV*ND];
__device__ __nv_bfloat16 g_Xtb[RT*ND];
__device__ __nv_bfloat16 g_Wvb[NE*ND];
__device__ __nv_bfloat16 g_Wtb[NE*ND];

__device__ __forceinline__ uint32_t smem_u32(const void* p){
    return (uint32_t)__cvta_generic_to_shared(p);
}
__device__ __forceinline__ void cp16(uint32_t dst, const void* src, int sz){
    asm volatile("cp.async.cg.shared.global [%0], [%1], 16, %2;\n"
                 :: "r"(dst), "l"(src), "r"(sz));
}
__device__ __forceinline__ void cp_commit(){ asm volatile("cp.async.commit_group;\n"); }
template<int N> __device__ __forceinline__ void cp_wait(){
    asm volatile("cp.async.wait_group %0;\n" :: "n"(N));
}
__device__ __forceinline__ void mma_bf16(float c[4], const uint32_t a[4], const uint32_t b[2]){
    asm volatile(
      "mma.sync.aligned.m16n8k16.row.col.f32.bf16.bf16.f32 "
      "{%0,%1,%2,%3},{%4,%5,%6,%7},{%8,%9},{%0,%1,%2,%3};\n"
      : "+f"(c[0]),"+f"(c[1]),"+f"(c[2]),"+f"(c[3])
      : "r"(a[0]),"r"(a[1]),"r"(a[2]),"r"(a[3]),"r"(b[0]),"r"(b[1]));
}
__device__ __forceinline__ void ldsm_x4(uint32_t r[4], uint32_t addr){
    asm volatile("ldmatrix.sync.aligned.m8n8.x4.shared.b16 {%0,%1,%2,%3}, [%4];"
                 : "=r"(r[0]), "=r"(r[1]), "=r"(r[2]), "=r"(r[3]) : "r"(addr));
}
__device__ __forceinline__ void ldsm_x2(uint32_t r[2], uint32_t addr){
    asm volatile("ldmatrix.sync.aligned.m8n8.x2.shared.b16 {%0,%1}, [%2];"
                 : "=r"(r[0]), "=r"(r[1]) : "r"(addr));
}

// ---------------------------------------------------------------------------
// K0: fp32 -> bf16 conversion for token GEMM inputs
// ---------------------------------------------------------------------------
__global__ __launch_bounds__(256) void cvt_kernel(
    const float* __restrict__ Xv, const float* __restrict__ Xt,
    const float* __restrict__ Wv, const float* __restrict__ Wt)
{
    const int NQ4 = ND/4;
    const int total = (RV + RT + 2*NE) * NQ4;
    int i = blockIdx.x*blockDim.x + threadIdx.x;
    if (i >= total) return;
    const float* src; __nv_bfloat16* dst; int off = i;
    if (off < RV*NQ4){ src = Xv; dst = g_Xvb; }
    else if ((off -= RV*NQ4) < RT*NQ4){ src = Xt; dst = g_Xtb; }
    else if ((off -= RT*NQ4) < NE*NQ4){ src = Wv; dst = g_Wvb; }
    else { off -= NE*NQ4; src = Wt; dst = g_Wtb; }
    float4 v = ((const float4*)src)[off];
    __nv_bfloat162 lo = __floats2bfloat162_rn(v.x, v.y);
    __nv_bfloat162 hi = __floats2bfloat162_rn(v.z, v.w);
    uint2 u; u.x = *(uint32_t*)&lo; u.y = *(uint32_t*)&hi;
    ((uint2*)dst)[off] = u;
}

// ---------------------------------------------------------------------------
// K1: cls projections (pure FP32, accuracy-critical outputs)
// ---------------------------------------------------------------------------
__global__ __launch_bounds__(256) void cls_gemm(
    const float* __restrict__ Xv, const float* __restrict__ Xt,
    const float* __restrict__ Wv, const float* __restrict__ bv,
    const float* __restrict__ Wt, const float* __restrict__ bt,
    float* __restrict__ out)
{
    __shared__ float Xs[16][64];
    __shared__ float Ws[64][65];
    const int which = blockIdx.z;
    const float* X    = which ? Xt : Xv;
    const float* W    = which ? Wt : Wv;
    const float* bias = which ? bt : bv;
    const int m0 = blockIdx.x * 16;
    const int n0 = blockIdx.y * 64;
    const int tid = threadIdx.x;
    float acc[4] = {0.f,0.f,0.f,0.f};
    const int jj = tid & 63;
    const int r4 = (tid >> 6) * 4;

    for (int k0 = 0; k0 < ND; k0 += 64){
        {
            int r = tid >> 4, kv = tid & 15;
            float4 x4 = *(const float4*)(X + (size_t)(m0 + r)*ND + k0 + kv*4);
            Xs[r][kv*4+0]=x4.x; Xs[r][kv*4+1]=x4.y; Xs[r][kv*4+2]=x4.z; Xs[r][kv*4+3]=x4.w;
        }
        #pragma unroll
        for (int i = 0; i < 4; i++){
            int seg = tid + 256*i; int r = seg >> 4, kv = seg & 15;
            float4 w4 = *(const float4*)(W + (size_t)(n0 + r)*ND + k0 + kv*4);
            Ws[r][kv*4+0]=w4.x; Ws[r][kv*4+1]=w4.y; Ws[r][kv*4+2]=w4.z; Ws[r][kv*4+3]=w4.w;
        }
        __syncthreads();
        #pragma unroll
        for (int k = 0; k < 64; k++){
            float w = Ws[jj][k];
            acc[0] += Xs[r4+0][k]*w;
            acc[1] += Xs[r4+1][k]*w;
            acc[2] += Xs[r4+2][k]*w;
            acc[3] += Xs[r4+3][k]*w;
        }
        __syncthreads();
    }
    float bb = bias[n0 + jj];
    float* o = out + (size_t)which*(NB*NE);
    #pragma unroll
    for (int i = 0; i < 4; i++)
        o[(size_t)(m0 + r4 + i)*NE + n0 + jj] = acc[i] + bb;
}

// ---------------------------------------------------------------------------
// K2: token projection GEMM (bf16 m16n8k16 + ldmatrix, single-sync pipeline).
// C[R,512] = Xb[R,768] @ Wb[512,768]^T + bias, fp32 out to g_Pv/g_Pt.
// CTA 128x128 tile, 8 warps (4wm x 2wn), warp tile 32x64. 12 k-chunks of 64.
// ---------------------------------------------------------------------------
#define ASTRIDE 144          // 72 bf16 per row
#define TOK_SMEM 73728       // A[2][128][72] + B[2][128][72] bf16

__global__ __launch_bounds__(256,2) void tok_gemm2(
    const float* __restrict__ bias, int R, int which)
{
    extern __shared__ char smem[];
    const uint32_t aB = smem_u32(smem);
    const uint32_t bB = aB + 36864;
    const __nv_bfloat16* X = which ? g_Xtb : g_Xvb;
    const __nv_bfloat16* W = which ? g_Wtb : g_Wvb;
    float* P = which ? g_Pt : g_Pv;
    const int m0 = blockIdx.x*128, n0 = blockIdx.y*128;
    const int tid = threadIdx.x, lane = tid & 31, warp = tid >> 5;
    const int wm = warp >> 1, wn = warp & 1;
    float acc[2][8][4] = {};

    const uint32_t a_lane = aB + (uint32_t)(wm*32 + (lane & 15))*ASTRIDE
                               + (uint32_t)((lane >> 4) & 1)*16;
    const uint32_t b_lane = bB + (uint32_t)(wn*64 + (lane & 7) + ((lane >> 4) & 1)*8)*ASTRIDE
                               + (uint32_t)((lane >> 3) & 1)*16;

    auto loadc = [&](int buf, int kc){
        const int k0 = kc*64;
        #pragma unroll
        for (int i = 0; i < 4; i++){          // A: 128 rows x 128B
            int seg = tid + 256*i; int r = seg >> 3, kv = seg & 7;
            uint32_t dst = aB + (uint32_t)buf*18432 + (uint32_t)r*ASTRIDE + (uint32_t)kv*16;
            int gr = m0 + r;
            const __nv_bfloat16* src = X + (size_t)(gr < R ? gr : 0)*ND + k0 + kv*8;
            cp16(dst, src, gr < R ? 16 : 0);
        }
        #pragma unroll
        for (int i = 0; i < 4; i++){          // B(W): 128 rows x 128B
            int seg = tid + 256*i; int r = seg >> 3, kv = seg & 7;
            uint32_t dst = bB + (uint32_t)buf*18432 + (uint32_t)r*ASTRIDE + (uint32_t)kv*16;
            const __nv_bfloat16* src = W + (size_t)(n0 + r)*ND + k0 + kv*8;
            cp16(dst, src, 16);
        }
    };

    loadc(0, 0); cp_commit();
    for (int kc = 0; kc < 12; kc++){
        cp_wait<0>();
        __syncthreads();                       // single sync: RAW + WAR
        if (kc < 11){ loadc((kc+1)&1, kc+1); cp_commit(); }
        const uint32_t abuf = a_lane + (uint32_t)(kc & 1)*18432;
        const uint32_t bbuf = b_lane + (uint32_t)(kc & 1)*18432;
        #pragma unroll
        for (int ks = 0; ks < 4; ks++){
            const uint32_t ko = (uint32_t)ks*32;
            uint32_t a[2][4], bfr[16];
            ldsm_x4(a[0], abuf + ko);
            ldsm_x4(a[1], abuf + 16*ASTRIDE + ko);
            ldsm_x4(&bfr[0],  bbuf + ko);
            ldsm_x4(&bfr[4],  bbuf + 16*ASTRIDE + ko);
            ldsm_x4(&bfr[8],  bbuf + 32*ASTRIDE + ko);
            ldsm_x4(&bfr[12], bbuf + 48*ASTRIDE + ko);
            #pragma unroll
            for (int mt = 0; mt < 2; mt++)
                #pragma unroll
                for (int nt = 0; nt < 8; nt++)
                    mma_bf16(acc[mt][nt], a[mt], &bfr[nt*2]);
        }
    }

    #pragma unroll
    for (int mt = 0; mt < 2; mt++){
        #pragma unroll
        for (int nt = 0; nt < 8; nt++){
            int r = m0 + wm*32 + mt*16 + (lane >> 2);
            int c = n0 + wn*64 + nt*8 + (lane & 3)*2;
            float b0 = bias[c], b1 = bias[c+1];
            if (r < R){
                P[(size_t)r*NE + c  ] = acc[mt][nt][0] + b0;
                P[(size_t)r*NE + c+1] = acc[mt][nt][1] + b1;
            }
            if (r + 8 < R){
                P[(size_t)(r+8)*NE + c  ] = acc[mt][nt][2] + b0;
                P[(size_t)(r+8)*NE + c+1] = acc[mt][nt][3] + b1;
            }
        }
    }
}

// ---------------------------------------------------------------------------
// K3: l2-normalize rows of P -> bf16 tokens
// ---------------------------------------------------------------------------
__global__ __launch_bounds__(256) void norm_kernel(int R, int which)
{
    const float* P = which ? g_Pt : g_Pv;
    __nv_bfloat16* O = which ? g_ttok : g_vtok;
    const int row  = blockIdx.x*8 + (threadIdx.x >> 5);
    const int lane = threadIdx.x & 31;
    if (row >= R) return;
    const float4* p = (const float4*)(P + (size_t)row*NE);
    float4 v[4]; float ss = 0.f;
    #pragma unroll
    for (int i = 0; i < 4; i++){
        v[i] = p[lane + 32*i];
        ss += v[i].x*v[i].x + v[i].y*v[i].y + v[i].z*v[i].z + v[i].w*v[i].w;
    }
    #pragma unroll
    for (int o = 16; o > 0; o >>= 1) ss += __shfl_xor_sync(0xffffffffu, ss, o);
    const float s = 1.f / fmaxf(sqrtf(ss), 1e-12f);
    uint2* ob = (uint2*)(O + (size_t)row*NE);
    #pragma unroll
    for (int i = 0; i < 4; i++){
        __nv_bfloat162 lo = __floats2bfloat162_rn(v[i].x*s, v[i].y*s);
        __nv_bfloat162 hi = __floats2bfloat162_rn(v[i].z*s, v[i].w*s);
        uint2 u; u.x = *(uint32_t*)&lo; u.y = *(uint32_t*)&hi;
        ob[lane + 32*i] = u;
    }
}

// ---------------------------------------------------------------------------
// K4: fine-grained similarity, M-split + q-pairing (R8 structure), with
// SINGLE sync per k-chunk (loadc issued after the sync; WAR+RAW share it).
// Grid (48, 96, 2); CTA 256 thr, 8 warps (4x2), warp tile 32x40 per q.
// ---------------------------------------------------------------------------
#define FG8_SMEM 83968

__global__ __launch_bounds__(256,2) void fg8_kernel(
    const int* __restrict__ text_length)
{
    extern __shared__ char smem[];
    const uint32_t aB = smem_u32(smem);
    const uint32_t bB = aB + 36864;
    float* rowp = (float*)smem;            // [2q][2wn][128]  epilogue overlay
    float* colp = (float*)(smem + 4096);   // [2q][4wm][80]
    float* red  = (float*)(smem + 6656);   // [2q][8]

    const int q0 = blockIdx.x*2, b = blockIdx.y, z = blockIdx.z;
    const int m_base = z*128;
    const int mrows  = z ? 80 : 128;
    const int vlim   = z ? 69 : 128;
    const int tid = threadIdx.x, lane = tid & 31, warp = tid >> 5;
    const int wm = warp >> 1, wn = warp & 1;
    const int mtcnt = (z == 0) ? 2 : (wm < 2 ? 2 : (wm == 2 ? 1 : 0));
    const __nv_bfloat16* Ag  = g_vtok + (size_t)b*NV*NE;
    const __nv_bfloat16* Bg0 = g_ttok + (size_t)q0*NT*NE;
    const __nv_bfloat16* Bg1 = g_ttok + (size_t)(q0+1)*NT*NE;
    float acc[2][2][5][4] = {};

    const uint32_t a_lane = aB + (uint32_t)(wm*32 + (lane & 15))*ASTRIDE
                               + (uint32_t)((lane >> 4) & 1)*16;
    const uint32_t b_pat  = (uint32_t)(wn*40 + (lane & 7) + ((lane >> 4) & 1)*8)*ASTRIDE
                               + (uint32_t)((lane >> 3) & 1)*16;

    auto loadc = [&](int buf, int kc){
        const int k0 = kc*64;
        for (int seg = tid; seg < mrows*8; seg += 256){
            int r = seg >> 3, kv = seg & 7;
            uint32_t dst = aB + (uint32_t)buf*18432 + (uint32_t)r*ASTRIDE + (uint32_t)kv*16;
            int gr = m_base + r;
            const __nv_bfloat16* src = Ag + (size_t)(gr < NV ? gr : 0)*NE + k0 + kv*8;
            cp16(dst, src, gr < NV ? 16 : 0);
        }
        #pragma unroll
        for (int i = 0; i < 5; i++){
            int seg = tid + 256*i;
            if (seg < 1280){
                int j  = seg / 640;
                int s2 = seg - j*640;
                int r = s2 >> 3, kv = s2 & 7;
                uint32_t dst = bB + (uint32_t)j*23040 + (uint32_t)buf*11520
                             + (uint32_t)r*ASTRIDE + (uint32_t)kv*16;
                const __nv_bfloat16* src = (j ? Bg1 : Bg0)
                                           + (size_t)(r < NT ? r : 0)*NE + k0 + kv*8;
                cp16(dst, src, r < NT ? 16 : 0);
            }
        }
    };

    loadc(0, 0); cp_commit();
    for (int kc = 0; kc < 8; kc++){
        cp_wait<0>();
        __syncthreads();                       // single sync: RAW + WAR
        if (kc < 7){ loadc((kc+1)&1, kc+1); cp_commit(); }
        const uint32_t abuf = a_lane + (uint32_t)(kc & 1)*18432;
        const uint32_t b0   = bB + b_pat + (uint32_t)(kc & 1)*11520;
        const uint32_t b1   = b0 + 23040;
        #pragma unroll
        for (int ks = 0; ks < 4; ks++){
            const uint32_t ko = (uint32_t)ks*32;
            uint32_t a[2][4], bf0[10], bf1[10];
            #pragma unroll
            for (int mt = 0; mt < 2; mt++)
                if (mt < mtcnt) ldsm_x4(a[mt], abuf + (uint32_t)mt*(16*ASTRIDE) + ko);
            ldsm_x4(&bf0[0], b0 + ko);
            ldsm_x4(&bf0[4], b0 + 16*ASTRIDE + ko);
            ldsm_x2(&bf0[8], b0 + 32*ASTRIDE + ko);
            ldsm_x4(&bf1[0], b1 + ko);
            ldsm_x4(&bf1[4], b1 + 16*ASTRIDE + ko);
            ldsm_x2(&bf1[8], b1 + 32*ASTRIDE + ko);
            #pragma unroll
            for (int mt = 0; mt < 2; mt++)
                if (mt < mtcnt){
                    #pragma unroll
                    for (int nt = 0; nt < 5; nt++){
                        mma_bf16(acc[0][mt][nt], a[mt], &bf0[nt*2]);
                        mma_bf16(acc[1][mt][nt], a[mt], &bf1[nt*2]);
                    }
                }
        }
    }
    __syncthreads();   // all warps done reading smem before epilogue overlays it

    // ---- epilogue: register-space masked reductions, per q ----
    const int len0 = text_length[q0];
    const int len1 = text_length[q0+1];
    const float NEG = -3.0e38f;

    #pragma unroll
    for (int j = 0; j < 2; j++){
        const int len = j ? len1 : len0;
        #pragma unroll
        for (int mt = 0; mt < 2; mt++){
            if (mt < mtcnt){
                float m0 = NEG, m1 = NEG;
                #pragma unroll
                for (int nt = 0; nt < 5; nt++){
                    int c0 = wn*40 + nt*8 + (lane & 3)*2;
                    if (c0 < len){ m0 = fmaxf(m0, acc[j][mt][nt][0]); m1 = fmaxf(m1, acc[j][mt][nt][2]); }
                    if (c0 + 1 < len){ m0 = fmaxf(m0, acc[j][mt][nt][1]); m1 = fmaxf(m1, acc[j][mt][nt][3]); }
                }
                m0 = fmaxf(m0, __shfl_xor_sync(0xffffffffu, m0, 1));
                m0 = fmaxf(m0, __shfl_xor_sync(0xffffffffu, m0, 2));
                m1 = fmaxf(m1, __shfl_xor_sync(0xffffffffu, m1, 1));
                m1 = fmaxf(m1, __shfl_xor_sync(0xffffffffu, m1, 2));
                if ((lane & 3) == 0){
                    int r = wm*32 + mt*16 + (lane >> 2);
                    rowp[j*256 + wn*128 + r]     = m0;
                    rowp[j*256 + wn*128 + r + 8] = m1;
                }
            } else if ((lane & 3) == 0){
                int r = wm*32 + mt*16 + (lane >> 2);
                rowp[j*256 + wn*128 + r]     = NEG;
                rowp[j*256 + wn*128 + r + 8] = NEG;
            }
        }
        #pragma unroll
        for (int nt = 0; nt < 5; nt++){
            float c0m = NEG, c1m = NEG;
            #pragma unroll
            for (int mt = 0; mt < 2; mt++){
                if (mt < mtcnt){
                    int gr = m_base + wm*32 + mt*16 + (lane >> 2);
                    if (gr < NV){ c0m = fmaxf(c0m, acc[j][mt][nt][0]); c1m = fmaxf(c1m, acc[j][mt][nt][1]); }
                    if (gr + 8 < NV){ c0m = fmaxf(c0m, acc[j][mt][nt][2]); c1m = fmaxf(c1m, acc[j][mt][nt][3]); }
                }
            }
            #pragma unroll
            for (int o = 4; o <= 16; o <<= 1){
                c0m = fmaxf(c0m, __shfl_xor_sync(0xffffffffu, c0m, o));
                c1m = fmaxf(c1m, __shfl_xor_sync(0xffffffffu, c1m, o));
            }
            if (lane < 4){
                int c = wn*40 + nt*8 + lane*2;
                colp[j*320 + wm*80 + c]     = c0m;
                colp[j*320 + wm*80 + c + 1] = c1m;
            }
        }
    }
    __syncthreads();

    #pragma unroll
    for (int j = 0; j < 2; j++){
        const int len = j ? len1 : len0;
        float contrib = 0.f;
        if (tid < vlim){
            float r = fmaxf(rowp[j*256 + tid], rowp[j*256 + 128 + tid]);
            if (len < NT) r = fmaxf(r, 0.f);
            contrib = r;
        }
        #pragma unroll
        for (int o = 16; o > 0; o >>= 1) contrib += __shfl_xor_sync(0xffffffffu, contrib, o);
        if (lane == 0) red[j*8 + warp] = contrib;
    }
    __syncthreads();
    if (warp < 2){
        float s = (lane < 8) ? red[warp*8 + lane] : 0.f;
        #pragma unroll
        for (int o = 4; o > 0; o >>= 1) s += __shfl_xor_sync(0xffffffffu, s, o);
        if (lane == 0) g_rs[z][b*NQ + q0 + warp] = s;
    }
    if (tid < 160){
        int j = tid / 80, t = tid - j*80;
        float cm = fmaxf(fmaxf(colp[j*320 + t],       colp[j*320 + 80 + t]),
                         fmaxf(colp[j*320 + 160 + t], colp[j*320 + 240 + t]));
        g_cm[z][(size_t)(b*NQ + q0 + j)*80 + t] = cm;
    }
}

// ---------------------------------------------------------------------------
// K5: finish — combine the two M-halves. One warp per (b,q).
// ---------------------------------------------------------------------------
__global__ __launch_bounds__(256) void finish_kernel(
    const int* __restrict__ text_length, float* __restrict__ out)
{
    const int gw = blockIdx.x*8 + (threadIdx.x >> 5);
    const int lane = threadIdx.x & 31;
    if (gw >= NB*NQ) return;
    const int q = gw % NQ, b = gw / NQ;
    const int len = text_length[q];
    float ts = 0.f;
    for (int t = lane; t < len; t += 32)
        ts += fmaxf(g_cm[0][(size_t)gw*80 + t], g_cm[1][(size_t)gw*80 + t]);
    #pragma unroll
    for (int o = 16; o > 0; o >>= 1) ts += __shfl_xor_sync(0xffffffffu, ts, o);
    if (lane == 0){
        out[2*NB*NE         + (size_t)b*NQ + q] = ts / (float)len;
        out[2*NB*NE + NB*NQ + (size_t)b*NQ + q] = (g_rs[0][gw] + g_rs[1][gw]) / (float)NV;
    }
}

extern "C" void kernel_launch(void* const* d_in, const int* in_sizes, int n_in,
                              void* d_out, int out_size) {
    const float* visual_cls    = (const float*)d_in[0];
    const float* visual_tokens = (const float*)d_in[1];
    const float* textual_cls   = (const float*)d_in[2];
    const float* textual_tokens= (const float*)d_in[3];
    const float* Wv_cls = (const float*)d_in[4];
    const float* bv_cls = (const float*)d_in[5];
    const float* Wt_cls = (const float*)d_in[6];
    const float* bt_cls = (const float*)d_in[7];
    const float* Wv_tok = (const float*)d_in[8];
    const float* bv_tok = (const float*)d_in[9];
    const float* Wt_tok = (const float*)d_in[10];
    const float* bt_tok = (const float*)d_in[11];
    const int*   text_length = (const int*)d_in[12];
    float* out = (float*)d_out;

    static bool attr_done = false;
    if (!attr_done){
        cudaFuncSetAttribute(fg8_kernel, cudaFuncAttributeMaxDynamicSharedMemorySize, FG8_SMEM);
        cudaFuncSetAttribute(tok_gemm2,  cudaFuncAttributeMaxDynamicSharedMemorySize, TOK_SMEM);
        attr_done = true;
    }

    cls_gemm<<<dim3(6,8,2), 256>>>(visual_cls, textual_cls,
                                   Wv_cls, bv_cls, Wt_cls, bt_cls, out);
    {
        const int total = (RV + RT + 2*NE) * (ND/4);
        cvt_kernel<<<(total + 255)/256, 256>>>(visual_tokens, textual_tokens,
                                               Wv_tok, Wt_tok);
    }
    tok_gemm2<<<dim3((RV+127)/128, 4), 256, TOK_SMEM>>>(bv_tok, RV, 0);
    tok_gemm2<<<dim3((RT+127)/128, 4), 256, TOK_SMEM>>>(bt_tok, RT, 1);
    norm_kernel<<<RV/8, 256>>>(RV, 0);
    norm_kernel<<<RT/8, 256>>>(RT, 1);
    fg8_kernel<<<dim3(NQ/2, NB, 2), 256, FG8_SMEM>>>(text_length);
    finish_kernel<<<(NB*NQ + 7)/8, 256>>>(text_length, out);
}

// round 13
// speedup vs baseline: 1.3082x; 1.0329x over previous
#include <cuda_runtime.h>
#include <cuda_bf16.h>
#include <stdint.h>

#define NB 96
#define NQ 96
#define NV 197
#define NT 77
#define ND 768
#define NE 512
#define RV (NB*NV)
#define RT (NQ*NT)

// scratch (static device globals — no allocation allowed)
__device__ float g_Pv[RV*NE];
__device__ float g_Pt[RT*NE];
__device__ __nv_bfloat16 g_vtok[RV*NE];
__device__ __nv_bfloat16 g_ttok[RT*NE];
__device__ float g_cm[2][NB*NQ*80];   // per-half column maxima
__device__ float g_rs[2][NB*NQ];      // per-half row-max partial sums
// bf16 copies of token-GEMM inputs
__device__ __nv_bfloat16 g_Xvb[RV*ND];
__device__ __nv_bfloat16 g_Xtb[RT*ND];
__device__ __nv_bfloat16 g_Wvb[NE*ND];
__device__ __nv_bfloat16 g_Wtb[NE*ND];

__device__ __forceinline__ uint32_t smem_u32(const void* p){
    return (uint32_t)__cvta_generic_to_shared(p);
}
__device__ __forceinline__ void cp16(uint32_t dst, const void* src, int sz){
    asm volatile("cp.async.cg.shared.global [%0], [%1], 16, %2;\n"
                 :: "r"(dst), "l"(src), "r"(sz));
}
__device__ __forceinline__ void cp_commit(){ asm volatile("cp.async.commit_group;\n"); }
template<int N> __device__ __forceinline__ void cp_wait(){
    asm volatile("cp.async.wait_group %0;\n" :: "n"(N));
}
__device__ __forceinline__ void mma_bf16(float c[4], const uint32_t a[4], const uint32_t b[2]){
    asm volatile(
      "mma.sync.aligned.m16n8k16.row.col.f32.bf16.bf16.f32 "
      "{%0,%1,%2,%3},{%4,%5,%6,%7},{%8,%9},{%0,%1,%2,%3};\n"
      : "+f"(c[0]),"+f"(c[1]),"+f"(c[2]),"+f"(c[3])
      : "r"(a[0]),"r"(a[1]),"r"(a[2]),"r"(a[3]),"r"(b[0]),"r"(b[1]));
}
__device__ __forceinline__ void ldsm_x4(uint32_t r[4], uint32_t addr){
    asm volatile("ldmatrix.sync.aligned.m8n8.x4.shared.b16 {%0,%1,%2,%3}, [%4];"
                 : "=r"(r[0]), "=r"(r[1]), "=r"(r[2]), "=r"(r[3]) : "r"(addr));
}
__device__ __forceinline__ void ldsm_x2(uint32_t r[2], uint32_t addr){
    asm volatile("ldmatrix.sync.aligned.m8n8.x2.shared.b16 {%0,%1}, [%2];"
                 : "=r"(r[0]), "=r"(r[1]) : "r"(addr));
}

// ---------------------------------------------------------------------------
// K0: fp32 -> bf16 conversion for token GEMM inputs
// ---------------------------------------------------------------------------
__global__ __launch_bounds__(256) void cvt_kernel(
    const float* __restrict__ Xv, const float* __restrict__ Xt,
    const float* __restrict__ Wv, const float* __restrict__ Wt)
{
    const int NQ4 = ND/4;
    const int total = (RV + RT + 2*NE) * NQ4;
    int i = blockIdx.x*blockDim.x + threadIdx.x;
    if (i >= total) return;
    const float* src; __nv_bfloat16* dst; int off = i;
    if (off < RV*NQ4){ src = Xv; dst = g_Xvb; }
    else if ((off -= RV*NQ4) < RT*NQ4){ src = Xt; dst = g_Xtb; }
    else if ((off -= RT*NQ4) < NE*NQ4){ src = Wv; dst = g_Wvb; }
    else { off -= NE*NQ4; src = Wt; dst = g_Wtb; }
    float4 v = ((const float4*)src)[off];
    __nv_bfloat162 lo = __floats2bfloat162_rn(v.x, v.y);
    __nv_bfloat162 hi = __floats2bfloat162_rn(v.z, v.w);
    uint2 u; u.x = *(uint32_t*)&lo; u.y = *(uint32_t*)&hi;
    ((uint2*)dst)[off] = u;
}

// ---------------------------------------------------------------------------
// K1: cls projections (pure FP32, accuracy-critical outputs)
// ---------------------------------------------------------------------------
__global__ __launch_bounds__(256) void cls_gemm(
    const float* __restrict__ Xv, const float* __restrict__ Xt,
    const float* __restrict__ Wv, const float* __restrict__ bv,
    const float* __restrict__ Wt, const float* __restrict__ bt,
    float* __restrict__ out)
{
    __shared__ float Xs[16][64];
    __shared__ float Ws[64][65];
    const int which = blockIdx.z;
    const float* X    = which ? Xt : Xv;
    const float* W    = which ? Wt : Wv;
    const float* bias = which ? bt : bv;
    const int m0 = blockIdx.x * 16;
    const int n0 = blockIdx.y * 64;
    const int tid = threadIdx.x;
    float acc[4] = {0.f,0.f,0.f,0.f};
    const int jj = tid & 63;
    const int r4 = (tid >> 6) * 4;

    for (int k0 = 0; k0 < ND; k0 += 64){
        {
            int r = tid >> 4, kv = tid & 15;
            float4 x4 = *(const float4*)(X + (size_t)(m0 + r)*ND + k0 + kv*4);
            Xs[r][kv*4+0]=x4.x; Xs[r][kv*4+1]=x4.y; Xs[r][kv*4+2]=x4.z; Xs[r][kv*4+3]=x4.w;
        }
        #pragma unroll
        for (int i = 0; i < 4; i++){
            int seg = tid + 256*i; int r = seg >> 4, kv = seg & 15;
            float4 w4 = *(const float4*)(W + (size_t)(n0 + r)*ND + k0 + kv*4);
            Ws[r][kv*4+0]=w4.x; Ws[r][kv*4+1]=w4.y; Ws[r][kv*4+2]=w4.z; Ws[r][kv*4+3]=w4.w;
        }
        __syncthreads();
        #pragma unroll
        for (int k = 0; k < 64; k++){
            float w = Ws[jj][k];
            acc[0] += Xs[r4+0][k]*w;
            acc[1] += Xs[r4+1][k]*w;
            acc[2] += Xs[r4+2][k]*w;
            acc[3] += Xs[r4+3][k]*w;
        }
        __syncthreads();
    }
    float bb = bias[n0 + jj];
    float* o = out + (size_t)which*(NB*NE);
    #pragma unroll
    for (int i = 0; i < 4; i++)
        o[(size_t)(m0 + r4 + i)*NE + n0 + jj] = acc[i] + bb;
}

// ---------------------------------------------------------------------------
// K2: merged token projection GEMM (bf16 m16n8k16 + ldmatrix, single-sync).
// grid.x in [0,148): visual rows; [148,206): textual rows. grid.y: n-tiles.
// ---------------------------------------------------------------------------
#define ASTRIDE 144          // 72 bf16 per row
#define TOK_SMEM 73728       // A[2][128][72] + B[2][128][72] bf16
#define TOK_VBLK 148         // ceil(RV/128)

__global__ __launch_bounds__(256,2) void tok_gemm3(
    const float* __restrict__ bv, const float* __restrict__ bt)
{
    extern __shared__ char smem[];
    const uint32_t aB = smem_u32(smem);
    const uint32_t bB = aB + 36864;
    const int which = (blockIdx.x >= TOK_VBLK) ? 1 : 0;
    const int bx = which ? (blockIdx.x - TOK_VBLK) : blockIdx.x;
    const int R = which ? RT : RV;
    const float* bias = which ? bt : bv;
    const __nv_bfloat16* X = which ? g_Xtb : g_Xvb;
    const __nv_bfloat16* W = which ? g_Wtb : g_Wvb;
    float* P = which ? g_Pt : g_Pv;
    const int m0 = bx*128, n0 = blockIdx.y*128;
    const int tid = threadIdx.x, lane = tid & 31, warp = tid >> 5;
    const int wm = warp >> 1, wn = warp & 1;
    float acc[2][8][4] = {};

    const uint32_t a_lane = aB + (uint32_t)(wm*32 + (lane & 15))*ASTRIDE
                               + (uint32_t)((lane >> 4) & 1)*16;
    const uint32_t b_lane = bB + (uint32_t)(wn*64 + (lane & 7) + ((lane >> 4) & 1)*8)*ASTRIDE
                               + (uint32_t)((lane >> 3) & 1)*16;

    auto loadc = [&](int buf, int kc){
        const int k0 = kc*64;
        #pragma unroll
        for (int i = 0; i < 4; i++){
            int seg = tid + 256*i; int r = seg >> 3, kv = seg & 7;
            uint32_t dst = aB + (uint32_t)buf*18432 + (uint32_t)r*ASTRIDE + (uint32_t)kv*16;
            int gr = m0 + r;
            const __nv_bfloat16* src = X + (size_t)(gr < R ? gr : 0)*ND + k0 + kv*8;
            cp16(dst, src, gr < R ? 16 : 0);
        }
        #pragma unroll
        for (int i = 0; i < 4; i++){
            int seg = tid + 256*i; int r = seg >> 3, kv = seg & 7;
            uint32_t dst = bB + (uint32_t)buf*18432 + (uint32_t)r*ASTRIDE + (uint32_t)kv*16;
            const __nv_bfloat16* src = W + (size_t)(n0 + r)*ND + k0 + kv*8;
            cp16(dst, src, 16);
        }
    };

    loadc(0, 0); cp_commit();
    for (int kc = 0; kc < 12; kc++){
        cp_wait<0>();
        __syncthreads();                       // single sync: RAW + WAR
        if (kc < 11){ loadc((kc+1)&1, kc+1); cp_commit(); }
        const uint32_t abuf = a_lane + (uint32_t)(kc & 1)*18432;
        const uint32_t bbuf = b_lane + (uint32_t)(kc & 1)*18432;
        #pragma unroll
        for (int ks = 0; ks < 4; ks++){
            const uint32_t ko = (uint32_t)ks*32;
            uint32_t a[2][4], bfr[16];
            ldsm_x4(a[0], abuf + ko);
            ldsm_x4(a[1], abuf + 16*ASTRIDE + ko);
            ldsm_x4(&bfr[0],  bbuf + ko);
            ldsm_x4(&bfr[4],  bbuf + 16*ASTRIDE + ko);
            ldsm_x4(&bfr[8],  bbuf + 32*ASTRIDE + ko);
            ldsm_x4(&bfr[12], bbuf + 48*ASTRIDE + ko);
            #pragma unroll
            for (int mt = 0; mt < 2; mt++)
                #pragma unroll
                for (int nt = 0; nt < 8; nt++)
                    mma_bf16(acc[mt][nt], a[mt], &bfr[nt*2]);
        }
    }

    #pragma unroll
    for (int mt = 0; mt < 2; mt++){
        #pragma unroll
        for (int nt = 0; nt < 8; nt++){
            int r = m0 + wm*32 + mt*16 + (lane >> 2);
            int c = n0 + wn*64 + nt*8 + (lane & 3)*2;
            float b0 = bias[c], b1 = bias[c+1];
            if (r < R){
                P[(size_t)r*NE + c  ] = acc[mt][nt][0] + b0;
                P[(size_t)r*NE + c+1] = acc[mt][nt][1] + b1;
            }
            if (r + 8 < R){
                P[(size_t)(r+8)*NE + c  ] = acc[mt][nt][2] + b0;
                P[(size_t)(r+8)*NE + c+1] = acc[mt][nt][3] + b1;
            }
        }
    }
}

// ---------------------------------------------------------------------------
// K3: merged l2-normalize (visual + textual rows in one grid)
// ---------------------------------------------------------------------------
__global__ __launch_bounds__(256) void norm_kernel2()
{
    int row  = blockIdx.x*8 + (threadIdx.x >> 5);
    const int lane = threadIdx.x & 31;
    const float* P; __nv_bfloat16* O;
    if (row < RV){ P = g_Pv; O = g_vtok; }
    else { row -= RV; if (row >= RT) return; P = g_Pt; O = g_ttok; }
    const float4* p = (const float4*)(P + (size_t)row*NE);
    float4 v[4]; float ss = 0.f;
    #pragma unroll
    for (int i = 0; i < 4; i++){
        v[i] = p[lane + 32*i];
        ss += v[i].x*v[i].x + v[i].y*v[i].y + v[i].z*v[i].z + v[i].w*v[i].w;
    }
    #pragma unroll
    for (int o = 16; o > 0; o >>= 1) ss += __shfl_xor_sync(0xffffffffu, ss, o);
    const float s = 1.f / fmaxf(sqrtf(ss), 1e-12f);
    uint2* ob = (uint2*)(O + (size_t)row*NE);
    #pragma unroll
    for (int i = 0; i < 4; i++){
        __nv_bfloat162 lo = __floats2bfloat162_rn(v[i].x*s, v[i].y*s);
        __nv_bfloat162 hi = __floats2bfloat162_rn(v[i].z*s, v[i].w*s);
        uint2 u; u.x = *(uint32_t*)&lo; u.y = *(uint32_t*)&hi;
        ob[lane + 32*i] = u;
    }
}

// ---------------------------------------------------------------------------
// K4: fine-grained similarity, templated on M-half Z. Static mtcnt/mrows for
// Z=0 (2/3 of work) -> guard-free mainloop SASS. Grid (48, 96); CTA 256 thr,
// 8 warps (4x2), warp tile 32x40 per q, two q's per CTA (A reused).
// Single sync per k-chunk.
// ---------------------------------------------------------------------------
#define FG9_SMEM 83968

template<int Z>
__global__ __launch_bounds__(256,2) void fg9_kernel(
    const int* __restrict__ text_length)
{
    extern __shared__ char smem[];
    const uint32_t aB = smem_u32(smem);
    const uint32_t bB = aB + 36864;
    float* rowp = (float*)smem;            // [2q][2wn][128]  epilogue overlay
    float* colp = (float*)(smem + 4096);   // [2q][4wm][80]
    float* red  = (float*)(smem + 6656);   // [2q][8]

    const int q0 = blockIdx.x*2, b = blockIdx.y;
    constexpr int m_base = Z*128;
    constexpr int mrows  = Z ? 80 : 128;
    constexpr int vlim   = Z ? 69 : 128;
    const int tid = threadIdx.x, lane = tid & 31, warp = tid >> 5;
    const int wm = warp >> 1, wn = warp & 1;
    const int mtcnt = (Z == 0) ? 2 : (wm < 2 ? 2 : (wm == 2 ? 1 : 0));
    const __nv_bfloat16* Ag  = g_vtok + (size_t)b*NV*NE;
    const __nv_bfloat16* Bg0 = g_ttok + (size_t)q0*NT*NE;
    const __nv_bfloat16* Bg1 = g_ttok + (size_t)(q0+1)*NT*NE;
    float acc[2][2][5][4] = {};

    const uint32_t a_lane = aB + (uint32_t)(wm*32 + (lane & 15))*ASTRIDE
                               + (uint32_t)((lane >> 4) & 1)*16;
    const uint32_t b_pat  = (uint32_t)(wn*40 + (lane & 7) + ((lane >> 4) & 1)*8)*ASTRIDE
                               + (uint32_t)((lane >> 3) & 1)*16;

    auto loadc = [&](int buf, int kc){
        const int k0 = kc*64;
        #pragma unroll
        for (int i = 0; i < (Z ? 3 : 4); i++){
            int seg = tid + 256*i;
            if (Z == 0 || seg < mrows*8){
                int r = seg >> 3, kv = seg & 7;
                uint32_t dst = aB + (uint32_t)buf*18432 + (uint32_t)r*ASTRIDE + (uint32_t)kv*16;
                int gr = m_base + r;
                const __nv_bfloat16* src = Ag + (size_t)(gr < NV ? gr : 0)*NE + k0 + kv*8;
                cp16(dst, src, gr < NV ? 16 : 0);
            }
        }
        #pragma unroll
        for (int i = 0; i < 5; i++){
            int seg = tid + 256*i;
            if (seg < 1280){
                int j  = seg / 640;
                int s2 = seg - j*640;
                int r = s2 >> 3, kv = s2 & 7;
                uint32_t dst = bB + (uint32_t)j*23040 + (uint32_t)buf*11520
                             + (uint32_t)r*ASTRIDE + (uint32_t)kv*16;
                const __nv_bfloat16* src = (j ? Bg1 : Bg0)
                                           + (size_t)(r < NT ? r : 0)*NE + k0 + kv*8;
                cp16(dst, src, r < NT ? 16 : 0);
            }
        }
    };

    loadc(0, 0); cp_commit();
    for (int kc = 0; kc < 8; kc++){
        cp_wait<0>();
        __syncthreads();                       // single sync: RAW + WAR
        if (kc < 7){ loadc((kc+1)&1, kc+1); cp_commit(); }
        const uint32_t abuf = a_lane + (uint32_t)(kc & 1)*18432;
        const uint32_t b0   = bB + b_pat + (uint32_t)(kc & 1)*11520;
        const uint32_t b1   = b0 + 23040;
        #pragma unroll
        for (int ks = 0; ks < 4; ks++){
            const uint32_t ko = (uint32_t)ks*32;
            uint32_t a[2][4], bf0[10], bf1[10];
            #pragma unroll
            for (int mt = 0; mt < 2; mt++)
                if (Z == 0 || mt < mtcnt) ldsm_x4(a[mt], abuf + (uint32_t)mt*(16*ASTRIDE) + ko);
            ldsm_x4(&bf0[0], b0 + ko);
            ldsm_x4(&bf0[4], b0 + 16*ASTRIDE + ko);
            ldsm_x2(&bf0[8], b0 + 32*ASTRIDE + ko);
            ldsm_x4(&bf1[0], b1 + ko);
            ldsm_x4(&bf1[4], b1 + 16*ASTRIDE + ko);
            ldsm_x2(&bf1[8], b1 + 32*ASTRIDE + ko);
            #pragma unroll
            for (int mt = 0; mt < 2; mt++)
                if (Z == 0 || mt < mtcnt){
                    #pragma unroll
                    for (int nt = 0; nt < 5; nt++){
                        mma_bf16(acc[0][mt][nt], a[mt], &bf0[nt*2]);
                        mma_bf16(acc[1][mt][nt], a[mt], &bf1[nt*2]);
                    }
                }
        }
    }
    __syncthreads();   // all warps done reading smem before epilogue overlays it

    // ---- epilogue: register-space masked reductions, per q ----
    const int len0 = text_length[q0];
    const int len1 = text_length[q0+1];
    const float NEG = -3.0e38f;

    #pragma unroll
    for (int j = 0; j < 2; j++){
        const int len = j ? len1 : len0;
        #pragma unroll
        for (int mt = 0; mt < 2; mt++){
            if (Z == 0 || mt < mtcnt){
                float m0 = NEG, m1 = NEG;
                #pragma unroll
                for (int nt = 0; nt < 5; nt++){
                    int c0 = wn*40 + nt*8 + (lane & 3)*2;
                    if (c0 < len){ m0 = fmaxf(m0, acc[j][mt][nt][0]); m1 = fmaxf(m1, acc[j][mt][nt][2]); }
                    if (c0 + 1 < len){ m0 = fmaxf(m0, acc[j][mt][nt][1]); m1 = fmaxf(m1, acc[j][mt][nt][3]); }
                }
                m0 = fmaxf(m0, __shfl_xor_sync(0xffffffffu, m0, 1));
                m0 = fmaxf(m0, __shfl_xor_sync(0xffffffffu, m0, 2));
                m1 = fmaxf(m1, __shfl_xor_sync(0xffffffffu, m1, 1));
                m1 = fmaxf(m1, __shfl_xor_sync(0xffffffffu, m1, 2));
                if ((lane & 3) == 0){
                    int r = wm*32 + mt*16 + (lane >> 2);
                    rowp[j*256 + wn*128 + r]     = m0;
                    rowp[j*256 + wn*128 + r + 8] = m1;
                }
            } else if ((lane & 3) == 0){
                int r = wm*32 + mt*16 + (lane >> 2);
                rowp[j*256 + wn*128 + r]     = NEG;
                rowp[j*256 + wn*128 + r + 8] = NEG;
            }
        }
        #pragma unroll
        for (int nt = 0; nt < 5; nt++){
            float c0m = NEG, c1m = NEG;
            #pragma unroll
            for (int mt = 0; mt < 2; mt++){
                if (Z == 0 || mt < mtcnt){
                    int gr = m_base + wm*32 + mt*16 + (lane >> 2);
                    if (gr < NV){ c0m = fmaxf(c0m, acc[j][mt][nt][0]); c1m = fmaxf(c1m, acc[j][mt][nt][1]); }
                    if (gr + 8 < NV){ c0m = fmaxf(c0m, acc[j][mt][nt][2]); c1m = fmaxf(c1m, acc[j][mt][nt][3]); }
                }
            }
            #pragma unroll
            for (int o = 4; o <= 16; o <<= 1){
                c0m = fmaxf(c0m, __shfl_xor_sync(0xffffffffu, c0m, o));
                c1m = fmaxf(c1m, __shfl_xor_sync(0xffffffffu, c1m, o));
            }
            if (lane < 4){
                int c = wn*40 + nt*8 + lane*2;
                colp[j*320 + wm*80 + c]     = c0m;
                colp[j*320 + wm*80 + c + 1] = c1m;
            }
        }
    }
    __syncthreads();

    #pragma unroll
    for (int j = 0; j < 2; j++){
        const int len = j ? len1 : len0;
        float contrib = 0.f;
        if (tid < vlim){
            float r = fmaxf(rowp[j*256 + tid], rowp[j*256 + 128 + tid]);
            if (len < NT) r = fmaxf(r, 0.f);
            contrib = r;
        }
        #pragma unroll
        for (int o = 16; o > 0; o >>= 1) contrib += __shfl_xor_sync(0xffffffffu, contrib, o);
        if (lane == 0) red[j*8 + warp] = contrib;
    }
    __syncthreads();
    if (warp < 2){
        float s = (lane < 8) ? red[warp*8 + lane] : 0.f;
        #pragma unroll
        for (int o = 4; o > 0; o >>= 1) s += __shfl_xor_sync(0xffffffffu, s, o);
        if (lane == 0) g_rs[Z][b*NQ + q0 + warp] = s;
    }
    if (tid < 160){
        int j = tid / 80, t = tid - j*80;
        float cm = fmaxf(fmaxf(colp[j*320 + t],       colp[j*320 + 80 + t]),
                         fmaxf(colp[j*320 + 160 + t], colp[j*320 + 240 + t]));
        g_cm[Z][(size_t)(b*NQ + q0 + j)*80 + t] = cm;
    }
}

// ---------------------------------------------------------------------------
// K5: finish — combine the two M-halves. One warp per (b,q).
// ---------------------------------------------------------------------------
__global__ __launch_bounds__(256) void finish_kernel(
    const int* __restrict__ text_length, float* __restrict__ out)
{
    const int gw = blockIdx.x*8 + (threadIdx.x >> 5);
    const int lane = threadIdx.x & 31;
    if (gw >= NB*NQ) return;
    const int q = gw % NQ, b = gw / NQ;
    const int len = text_length[q];
    float ts = 0.f;
    for (int t = lane; t < len; t += 32)
        ts += fmaxf(g_cm[0][(size_t)gw*80 + t], g_cm[1][(size_t)gw*80 + t]);
    #pragma unroll
    for (int o = 16; o > 0; o >>= 1) ts += __shfl_xor_sync(0xffffffffu, ts, o);
    if (lane == 0){
        out[2*NB*NE         + (size_t)b*NQ + q] = ts / (float)len;
        out[2*NB*NE + NB*NQ + (size_t)b*NQ + q] = (g_rs[0][gw] + g_rs[1][gw]) / (float)NV;
    }
}

extern "C" void kernel_launch(void* const* d_in, const int* in_sizes, int n_in,
                              void* d_out, int out_size) {
    const float* visual_cls    = (const float*)d_in[0];
    const float* visual_tokens = (const float*)d_in[1];
    const float* textual_cls   = (const float*)d_in[2];
    const float* textual_tokens= (const float*)d_in[3];
    const float* Wv_cls = (const float*)d_in[4];
    const float* bv_cls = (const float*)d_in[5];
    const float* Wt_cls = (const float*)d_in[6];
    const float* bt_cls = (const float*)d_in[7];
    const float* Wv_tok = (const float*)d_in[8];
    const float* bv_tok = (const float*)d_in[9];
    const float* Wt_tok = (const float*)d_in[10];
    const float* bt_tok = (const float*)d_in[11];
    const int*   text_length = (const int*)d_in[12];
    float* out = (float*)d_out;

    static bool attr_done = false;
    if (!attr_done){
        cudaFuncSetAttribute(fg9_kernel<0>, cudaFuncAttributeMaxDynamicSharedMemorySize, FG9_SMEM);
        cudaFuncSetAttribute(fg9_kernel<1>, cudaFuncAttributeMaxDynamicSharedMemorySize, FG9_SMEM);
        cudaFuncSetAttribute(tok_gemm3,     cudaFuncAttributeMaxDynamicSharedMemorySize, TOK_SMEM);
        attr_done = true;
    }

    {
        const int total = (RV + RT + 2*NE) * (ND/4);
        cvt_kernel<<<(total + 255)/256, 256>>>(visual_tokens, textual_tokens,
                                               Wv_tok, Wt_tok);
    }
    tok_gemm3<<<dim3(TOK_VBLK + (RT+127)/128, 4), 256, TOK_SMEM>>>(bv_tok, bt_tok);
    norm_kernel2<<<(RV + RT)/8, 256>>>();
    fg9_kernel<0><<<dim3(NQ/2, NB), 256, FG9_SMEM>>>(text_length);
    fg9_kernel<1><<<dim3(NQ/2, NB), 256, FG9_SMEM>>>(text_length);
    cls_gemm<<<dim3(6,8,2), 256>>>(visual_cls, textual_cls,
                                   Wv_cls, bv_cls, Wt_cls, bt_cls, out);
    finish_kernel<<<(NB*NQ + 7)/8, 256>>>(text_length, out);
}